// round 1
// baseline (speedup 1.0000x reference)
#include <cuda_runtime.h>
#include <math.h>

#define NN 50000
#define EE 150000
#define NODE_IN 64
#define EDGE_IN 16
#define D 32
#define EH 128
#define STEPS 3

// Scratch (device globals — no allocation APIs allowed)
__device__ float g_a[EE * EH];                 // edge hidden, 76.8 MB
__device__ float g_Wm[(size_t)EE * D * D];     // per-edge matrices, 614 MB
__device__ float g_h[NN * D];                  // node state
__device__ float g_agg[NN * D];                // scatter accumulator

// ---------------------------------------------------------------------------
// K1: a_e = relu(edge_attr @ We1 + be1)   [E,16]@[16,128]
// one edge per 128-thread block
__global__ void k_edge_hidden(const float* __restrict__ ea,
                              const float* __restrict__ We1,
                              const float* __restrict__ be1) {
    int e = blockIdx.x;
    int t = threadIdx.x;            // 0..127
    __shared__ float s_ea[EDGE_IN];
    if (t < EDGE_IN) s_ea[t] = ea[e * EDGE_IN + t];
    __syncthreads();
    float acc = be1[t];
#pragma unroll
    for (int i = 0; i < EDGE_IN; i++)
        acc = fmaf(s_ea[i], We1[i * EH + t], acc);
    g_a[e * EH + t] = fmaxf(acc, 0.0f);
}

// ---------------------------------------------------------------------------
// K2: g_Wm = g_a [E,128] @ We2 [128,1024] + be2
// classic 128x128x8 fp32 SGEMM, 256 threads, 8x8 microtile
__global__ __launch_bounds__(256) void k_wm_gemm(const float* __restrict__ B,
                                                 const float* __restrict__ bias) {
    const int M = EE;
    __shared__ float As[8][128];
    __shared__ float Bs[8][128];
    int tid = threadIdx.x;
    int rowBase = blockIdx.x * 128;
    int colBase = blockIdx.y * 128;

    int arow = tid >> 1;            // 0..127
    int acol = (tid & 1) * 4;       // 0 or 4
    int brow = tid >> 5;            // 0..7
    int bcol = (tid & 31) * 4;      // 0..124

    int ty = tid >> 4;              // 0..15  -> rows ty*8..
    int tx = tid & 15;              // 0..15  -> cols tx*8..

    float acc[8][8];
#pragma unroll
    for (int r = 0; r < 8; r++)
#pragma unroll
        for (int c = 0; c < 8; c++) acc[r][c] = 0.0f;

    for (int kt = 0; kt < 128; kt += 8) {
        // load A tile (guard M)
        float4 va = make_float4(0.f, 0.f, 0.f, 0.f);
        int gr = rowBase + arow;
        if (gr < M) va = *(const float4*)(g_a + (size_t)gr * EH + kt + acol);
        As[acol + 0][arow] = va.x;
        As[acol + 1][arow] = va.y;
        As[acol + 2][arow] = va.z;
        As[acol + 3][arow] = va.w;
        // load B tile (exact)
        float4 vb = *(const float4*)(B + (size_t)(kt + brow) * 1024 + colBase + bcol);
        *(float4*)&Bs[brow][bcol] = vb;
        __syncthreads();
#pragma unroll
        for (int k = 0; k < 8; k++) {
            float ra[8], rb[8];
#pragma unroll
            for (int r = 0; r < 8; r++) ra[r] = As[k][ty * 8 + r];
#pragma unroll
            for (int c = 0; c < 8; c++) rb[c] = Bs[k][tx * 8 + c];
#pragma unroll
            for (int r = 0; r < 8; r++)
#pragma unroll
                for (int c = 0; c < 8; c++)
                    acc[r][c] = fmaf(ra[r], rb[c], acc[r][c]);
        }
        __syncthreads();
    }
    // epilogue: +bias, store
#pragma unroll
    for (int r = 0; r < 8; r++) {
        int grow = rowBase + ty * 8 + r;
        if (grow >= M) break;
#pragma unroll
        for (int c = 0; c < 8; c += 4) {
            int gcol = colBase + tx * 8 + c;
            float4 v;
            v.x = acc[r][c + 0] + bias[gcol + 0];
            v.y = acc[r][c + 1] + bias[gcol + 1];
            v.z = acc[r][c + 2] + bias[gcol + 2];
            v.w = acc[r][c + 3] + bias[gcol + 3];
            *(float4*)(g_Wm + (size_t)grow * 1024 + gcol) = v;
        }
    }
}

// ---------------------------------------------------------------------------
// K3: h = relu(x @ Wn + bn)  [N,64]@[64,32]; also zero g_agg for step 0.
// warp per node
__global__ void k_node_init(const float* __restrict__ x,
                            const float* __restrict__ Wn,
                            const float* __restrict__ bn) {
    int warp = (blockIdx.x * blockDim.x + threadIdx.x) >> 5;
    int lane = threadIdx.x & 31;
    if (warp >= NN) return;
    float x0 = x[warp * NODE_IN + lane];
    float x1 = x[warp * NODE_IN + 32 + lane];
    float acc = bn[lane];
#pragma unroll
    for (int i = 0; i < 32; i++) {
        acc = fmaf(__shfl_sync(0xffffffffu, x0, i), Wn[i * D + lane], acc);
        acc = fmaf(__shfl_sync(0xffffffffu, x1, i), Wn[(i + 32) * D + lane], acc);
    }
    g_h[warp * D + lane] = fmaxf(acc, 0.0f);
    g_agg[warp * D + lane] = 0.0f;
}

// ---------------------------------------------------------------------------
// K5: per-edge m = h[src]^T Wm_e ; atomicAdd into g_agg[dst]
// warp per edge; lane = output channel o
__global__ void k_message(const int* __restrict__ src, const int* __restrict__ dst) {
    int warp = (blockIdx.x * blockDim.x + threadIdx.x) >> 5;
    int lane = threadIdx.x & 31;
    if (warp >= EE) return;
    int s = src[warp];
    int d = dst[warp];
    float hv = g_h[s * D + lane];
    const float* W = g_Wm + (size_t)warp * 1024;
    float m = 0.0f;
#pragma unroll
    for (int i = 0; i < 32; i++)
        m = fmaf(__shfl_sync(0xffffffffu, hv, i), __ldg(W + i * D + lane), m);
    atomicAdd(g_agg + d * D + lane, m);
}

// ---------------------------------------------------------------------------
// K6: conv = relu(agg + h@Wroot + bconv); GRU(conv, h). Re-zeros agg for next step.
// warp per node; GRU weights pre-transposed into smem for conflict-free reads.
__global__ __launch_bounds__(256) void k_gru(const float* __restrict__ Wroot,
                                             const float* __restrict__ bconv,
                                             const float* __restrict__ Wih,
                                             const float* __restrict__ Whh,
                                             const float* __restrict__ bih,
                                             const float* __restrict__ bhh,
                                             float* __restrict__ out_ext,
                                             int use_ext) {
    __shared__ float sWihT[32 * 96];
    __shared__ float sWhhT[32 * 96];
    int t = threadIdx.x;
    for (int idx = t; idx < 96 * 32; idx += blockDim.x) {
        int g = idx / 32, i = idx % 32;
        sWihT[i * 96 + g] = Wih[idx];   // Wih row-major [96][32]
        sWhhT[i * 96 + g] = Whh[idx];
    }
    __syncthreads();

    int warp = (blockIdx.x * blockDim.x + t) >> 5;
    int lane = t & 31;
    if (warp >= NN) return;

    float hv = g_h[warp * D + lane];
    float c = g_agg[warp * D + lane] + bconv[lane];
    g_agg[warp * D + lane] = 0.0f;              // prep next step
#pragma unroll
    for (int i = 0; i < 32; i++)
        c = fmaf(__shfl_sync(0xffffffffu, hv, i), Wroot[i * D + lane], c);
    c = fmaxf(c, 0.0f);

    float gr = bih[lane], gz = bih[32 + lane], gn = bih[64 + lane];
    float hr = bhh[lane], hz = bhh[32 + lane], hn = bhh[64 + lane];
#pragma unroll
    for (int i = 0; i < 32; i++) {
        float cv  = __shfl_sync(0xffffffffu, c, i);
        float hvi = __shfl_sync(0xffffffffu, hv, i);
        const float* wi = sWihT + i * 96;
        const float* wh = sWhhT + i * 96;
        gr = fmaf(cv, wi[lane], gr);
        gz = fmaf(cv, wi[32 + lane], gz);
        gn = fmaf(cv, wi[64 + lane], gn);
        hr = fmaf(hvi, wh[lane], hr);
        hz = fmaf(hvi, wh[32 + lane], hz);
        hn = fmaf(hvi, wh[64 + lane], hn);
    }
    float r  = 1.0f / (1.0f + expf(-(gr + hr)));
    float z  = 1.0f / (1.0f + expf(-(gz + hz)));
    float nn = tanhf(gn + r * hn);
    float hnew = (1.0f - z) * nn + z * hv;

    if (use_ext) out_ext[warp * D + lane] = hnew;
    else         g_h[warp * D + lane] = hnew;
}

// ---------------------------------------------------------------------------
extern "C" void kernel_launch(void* const* d_in, const int* in_sizes, int n_in,
                              void* d_out, int out_size) {
    const float* x     = (const float*)d_in[0];
    const int*   ei    = (const int*)d_in[1];
    const float* ea    = (const float*)d_in[2];
    const float* Wn    = (const float*)d_in[3];
    const float* bn    = (const float*)d_in[4];
    const float* We1   = (const float*)d_in[5];
    const float* be1   = (const float*)d_in[6];
    const float* We2   = (const float*)d_in[7];
    const float* be2   = (const float*)d_in[8];
    const float* Wroot = (const float*)d_in[9];
    const float* bconv = (const float*)d_in[10];
    const float* Wih   = (const float*)d_in[11];
    const float* Whh   = (const float*)d_in[12];
    const float* bih   = (const float*)d_in[13];
    const float* bhh   = (const float*)d_in[14];
    const int* src = ei;
    const int* dst = ei + EE;
    float* out = (float*)d_out;

    // edge network (once)
    k_edge_hidden<<<EE, 128>>>(ea, We1, be1);
    dim3 ggrid((EE + 127) / 128, 1024 / 128);
    k_wm_gemm<<<ggrid, 256>>>(We2, be2);

    // node init (+ agg zero)
    k_node_init<<<(NN * 32 + 255) / 256, 256>>>(x, Wn, bn);

    for (int s = 0; s < STEPS; s++) {
        k_message<<<(EE * 32 + 255) / 256, 256>>>(src, dst);
        int last = (s == STEPS - 1) ? 1 : 0;
        k_gru<<<(NN * 32 + 255) / 256, 256>>>(Wroot, bconv, Wih, Whh, bih, bhh,
                                              out, last);
    }
}

// round 5
// speedup vs baseline: 1.5162x; 1.5162x over previous
#include <cuda_runtime.h>
#include <cuda_bf16.h>
#include <cuda_fp16.h>
#include <cstdint>
#include <math.h>

#define NN 50000
#define EE 150000
#define NODE_IN 64
#define EDGE_IN 16
#define D 32
#define EH 128
#define STEPS 3

// Scratch (device globals — no allocation APIs allowed)
__device__ __nv_bfloat16 g_a_hi[(size_t)EE * EH];   // 38.4 MB
__device__ __nv_bfloat16 g_a_lo[(size_t)EE * EH];   // 38.4 MB
__device__ __nv_bfloat16 g_WT_hi[1024 * EH];        // We2^T hi, 256 KB
__device__ __nv_bfloat16 g_WT_lo[1024 * EH];        // We2^T lo, 256 KB
__device__ __half g_Wm_h[(size_t)EE * D * D];       // per-edge matrices, 307 MB (fp16)
__device__ float g_h[NN * D];                       // node state
__device__ float g_agg[NN * D];                     // scatter accumulator

// ===========================================================================
// K1: a_e = relu(edge_attr @ We1 + be1), emitted as bf16 hi/lo split
// ===========================================================================
__global__ void k_edge_hidden(const float* __restrict__ ea,
                              const float* __restrict__ We1,
                              const float* __restrict__ be1) {
    int e = blockIdx.x;
    int t = threadIdx.x;            // 0..127
    __shared__ float s_ea[EDGE_IN];
    if (t < EDGE_IN) s_ea[t] = ea[e * EDGE_IN + t];
    __syncthreads();
    float acc = be1[t];
#pragma unroll
    for (int i = 0; i < EDGE_IN; i++)
        acc = fmaf(s_ea[i], We1[i * EH + t], acc);
    float a = fmaxf(acc, 0.0f);
    __nv_bfloat16 hi = __float2bfloat16(a);
    float lo = a - __bfloat162float(hi);
    g_a_hi[(size_t)e * EH + t] = hi;
    g_a_lo[(size_t)e * EH + t] = __float2bfloat16(lo);
}

// ===========================================================================
// K1b: We2^T hi/lo split:  WT[n][k] = We2[k][n]
// ===========================================================================
__global__ void k_we2t(const float* __restrict__ We2) {
    int n = blockIdx.x;             // 0..1023
    int k = threadIdx.x;            // 0..127
    float v = We2[(size_t)k * 1024 + n];
    __nv_bfloat16 hi = __float2bfloat16(v);
    float lo = v - __bfloat162float(hi);
    g_WT_hi[n * EH + k] = hi;
    g_WT_lo[n * EH + k] = __float2bfloat16(lo);
}

// ===========================================================================
// K2: Wm = a [E,128] @ We2 [128,1024] + be2, via mma.sync bf16 2-term split.
// CTA = 128 rows x 1024 cols (8 N-tiles of 128). 256 threads = 8 warps,
// warp tile 64x32 (warp grid 2x4). fp16 output.
// ===========================================================================
#define APITCH 136                         // bf16 elems per smem row (conflict-free)
#define TILE_BYTES (128 * APITCH * 2)      // 34816
#define OFF_BIAS 0
#define OFF_A_HI 4096
#define OFF_A_LO (OFF_A_HI + TILE_BYTES)
#define OFF_B_HI (OFF_A_LO + TILE_BYTES)
#define OFF_B_LO (OFF_B_HI + TILE_BYTES)
#define SM_TOTAL (OFF_B_LO + TILE_BYTES)   // 143360

__device__ __forceinline__ void mma16816(float* c, const uint32_t* a, const uint32_t* b) {
    asm volatile(
        "mma.sync.aligned.m16n8k16.row.col.f32.bf16.bf16.f32 "
        "{%0,%1,%2,%3}, {%4,%5,%6,%7}, {%8,%9}, {%0,%1,%2,%3};"
        : "+f"(c[0]), "+f"(c[1]), "+f"(c[2]), "+f"(c[3])
        : "r"(a[0]), "r"(a[1]), "r"(a[2]), "r"(a[3]), "r"(b[0]), "r"(b[1]));
}

__global__ void __launch_bounds__(256, 1) k_wm_mma(const float* __restrict__ bias) {
    extern __shared__ char smem[];
    float* sbias = (float*)(smem + OFF_BIAS);
    int tid = threadIdx.x;
    int wid = tid >> 5;
    int lane = tid & 31;
    int g = lane >> 2;          // group id (0..7)
    int tig = lane & 3;         // thread in group
    int wm = wid >> 2;          // 0..1 (64-row warp tile)
    int wn = wid & 3;           // 0..3 (32-col warp tile)
    int rowBase = blockIdx.x * 128;

    // bias -> smem (once)
    for (int i = tid; i < 1024; i += 256) sbias[i] = bias[i];

    // ---- stage A (hi/lo), 128 rows x 128 k, zero-pad past EE ----
    for (int idx = tid; idx < 2048; idx += 256) {   // 16B chunks: 128 rows x 16
        int r = idx >> 4;
        int c = (idx & 15) * 8;
        int grow = rowBase + r;
        uint4 vh = make_uint4(0u, 0u, 0u, 0u), vl = vh;
        if (grow < EE) {
            vh = *(const uint4*)(g_a_hi + (size_t)grow * EH + c);
            vl = *(const uint4*)(g_a_lo + (size_t)grow * EH + c);
        }
        *(uint4*)(smem + OFF_A_HI + (r * APITCH + c) * 2) = vh;
        *(uint4*)(smem + OFF_A_LO + (r * APITCH + c) * 2) = vl;
    }

    for (int nt = 0; nt < 8; nt++) {
        int nBase = nt * 128;
        // ---- stage B tile [128 n-rows][128 k] hi/lo ----
        for (int idx = tid; idx < 2048; idx += 256) {
            int r = idx >> 4;
            int c = (idx & 15) * 8;
            *(uint4*)(smem + OFF_B_HI + (r * APITCH + c) * 2) =
                *(const uint4*)(g_WT_hi + (size_t)(nBase + r) * EH + c);
            *(uint4*)(smem + OFF_B_LO + (r * APITCH + c) * 2) =
                *(const uint4*)(g_WT_lo + (size_t)(nBase + r) * EH + c);
        }
        __syncthreads();

        float acc[4][4][4];
#pragma unroll
        for (int mi = 0; mi < 4; mi++)
#pragma unroll
            for (int ni = 0; ni < 4; ni++)
#pragma unroll
                for (int q = 0; q < 4; q++) acc[mi][ni][q] = 0.0f;

#pragma unroll 1
        for (int ks = 0; ks < 8; ks++) {
            int k0 = ks * 16;
            uint32_t ah[4][4], al[4][4], bh[4][2], bl[4][2];
#pragma unroll
            for (int mi = 0; mi < 4; mi++) {
                int r0 = wm * 64 + mi * 16 + g;
                int o00 = (r0 * APITCH + k0 + tig * 2) * 2;
                int o10 = ((r0 + 8) * APITCH + k0 + tig * 2) * 2;
                ah[mi][0] = *(const uint32_t*)(smem + OFF_A_HI + o00);
                ah[mi][1] = *(const uint32_t*)(smem + OFF_A_HI + o10);
                ah[mi][2] = *(const uint32_t*)(smem + OFF_A_HI + o00 + 16);
                ah[mi][3] = *(const uint32_t*)(smem + OFF_A_HI + o10 + 16);
                al[mi][0] = *(const uint32_t*)(smem + OFF_A_LO + o00);
                al[mi][1] = *(const uint32_t*)(smem + OFF_A_LO + o10);
                al[mi][2] = *(const uint32_t*)(smem + OFF_A_LO + o00 + 16);
                al[mi][3] = *(const uint32_t*)(smem + OFF_A_LO + o10 + 16);
            }
#pragma unroll
            for (int ni = 0; ni < 4; ni++) {
                int bn = wn * 32 + ni * 8 + g;
                int ob = (bn * APITCH + k0 + tig * 2) * 2;
                bh[ni][0] = *(const uint32_t*)(smem + OFF_B_HI + ob);
                bh[ni][1] = *(const uint32_t*)(smem + OFF_B_HI + ob + 16);
                bl[ni][0] = *(const uint32_t*)(smem + OFF_B_LO + ob);
                bl[ni][1] = *(const uint32_t*)(smem + OFF_B_LO + ob + 16);
            }
#pragma unroll
            for (int mi = 0; mi < 4; mi++)
#pragma unroll
                for (int ni = 0; ni < 4; ni++) {
                    mma16816(acc[mi][ni], ah[mi], bh[ni]);
                    mma16816(acc[mi][ni], ah[mi], bl[ni]);
                    mma16816(acc[mi][ni], al[mi], bh[ni]);
                }
        }

        // ---- epilogue: +bias, cvt fp16, store ----
#pragma unroll
        for (int mi = 0; mi < 4; mi++) {
            int row0 = rowBase + wm * 64 + mi * 16 + g;
#pragma unroll
            for (int ni = 0; ni < 4; ni++) {
                int col = nBase + wn * 32 + ni * 8 + tig * 2;
                float b0 = sbias[col], b1 = sbias[col + 1];
                if (row0 < EE) {
                    __half2 v = __floats2half2_rn(acc[mi][ni][0] + b0, acc[mi][ni][1] + b1);
                    *(__half2*)(g_Wm_h + (size_t)row0 * 1024 + col) = v;
                }
                if (row0 + 8 < EE) {
                    __half2 v = __floats2half2_rn(acc[mi][ni][2] + b0, acc[mi][ni][3] + b1);
                    *(__half2*)(g_Wm_h + (size_t)(row0 + 8) * 1024 + col) = v;
                }
            }
        }
        __syncthreads();   // all frag loads done before B is overwritten
    }
}

// ===========================================================================
// K3: h = relu(x @ Wn + bn); zero g_agg
// ===========================================================================
__global__ void k_node_init(const float* __restrict__ x,
                            const float* __restrict__ Wn,
                            const float* __restrict__ bn) {
    int warp = (blockIdx.x * blockDim.x + threadIdx.x) >> 5;
    int lane = threadIdx.x & 31;
    if (warp >= NN) return;
    float x0 = x[warp * NODE_IN + lane];
    float x1 = x[warp * NODE_IN + 32 + lane];
    float acc = bn[lane];
#pragma unroll
    for (int i = 0; i < 32; i++) {
        acc = fmaf(__shfl_sync(0xffffffffu, x0, i), Wn[i * D + lane], acc);
        acc = fmaf(__shfl_sync(0xffffffffu, x1, i), Wn[(i + 32) * D + lane], acc);
    }
    g_h[warp * D + lane] = fmaxf(acc, 0.0f);
    g_agg[warp * D + lane] = 0.0f;
}

// ===========================================================================
// K5: per-edge m = h[src]^T Wm_e (fp16) ; atomicAdd into g_agg[dst]
// ===========================================================================
__global__ void k_message(const int* __restrict__ src, const int* __restrict__ dst) {
    int warp = (blockIdx.x * blockDim.x + threadIdx.x) >> 5;
    int lane = threadIdx.x & 31;
    if (warp >= EE) return;
    int s = src[warp];
    int d = dst[warp];
    float hv = g_h[s * D + lane];
    const __half* W = g_Wm_h + (size_t)warp * 1024;
    float m = 0.0f;
#pragma unroll
    for (int i = 0; i < 32; i++)
        m = fmaf(__shfl_sync(0xffffffffu, hv, i), __half2float(__ldg(W + i * D + lane)), m);
    atomicAdd(g_agg + d * D + lane, m);
}

// ===========================================================================
// K6: conv = relu(agg + h@Wroot + bconv); GRU(conv, h); re-zero agg
// ===========================================================================
__global__ void __launch_bounds__(256) k_gru(const float* __restrict__ Wroot,
                                             const float* __restrict__ bconv,
                                             const float* __restrict__ Wih,
                                             const float* __restrict__ Whh,
                                             const float* __restrict__ bih,
                                             const float* __restrict__ bhh,
                                             float* __restrict__ out_ext,
                                             int use_ext) {
    __shared__ float sWihT[32 * 96];
    __shared__ float sWhhT[32 * 96];
    int t = threadIdx.x;
    for (int idx = t; idx < 96 * 32; idx += blockDim.x) {
        int gg = idx / 32, i = idx % 32;
        sWihT[i * 96 + gg] = Wih[idx];
        sWhhT[i * 96 + gg] = Whh[idx];
    }
    __syncthreads();

    int warp = (blockIdx.x * blockDim.x + t) >> 5;
    int lane = t & 31;
    if (warp >= NN) return;

    float hv = g_h[warp * D + lane];
    float c = g_agg[warp * D + lane] + bconv[lane];
    g_agg[warp * D + lane] = 0.0f;
#pragma unroll
    for (int i = 0; i < 32; i++)
        c = fmaf(__shfl_sync(0xffffffffu, hv, i), Wroot[i * D + lane], c);
    c = fmaxf(c, 0.0f);

    float gr = bih[lane], gz = bih[32 + lane], gn = bih[64 + lane];
    float hr = bhh[lane], hz = bhh[32 + lane], hn = bhh[64 + lane];
#pragma unroll
    for (int i = 0; i < 32; i++) {
        float cv  = __shfl_sync(0xffffffffu, c, i);
        float hvi = __shfl_sync(0xffffffffu, hv, i);
        const float* wi = sWihT + i * 96;
        const float* wh = sWhhT + i * 96;
        gr = fmaf(cv, wi[lane], gr);
        gz = fmaf(cv, wi[32 + lane], gz);
        gn = fmaf(cv, wi[64 + lane], gn);
        hr = fmaf(hvi, wh[lane], hr);
        hz = fmaf(hvi, wh[32 + lane], hz);
        hn = fmaf(hvi, wh[64 + lane], hn);
    }
    float r  = 1.0f / (1.0f + expf(-(gr + hr)));
    float z  = 1.0f / (1.0f + expf(-(gz + hz)));
    float nn = tanhf(gn + r * hn);
    float hnew = (1.0f - z) * nn + z * hv;

    if (use_ext) out_ext[warp * D + lane] = hnew;
    else         g_h[warp * D + lane] = hnew;
}

// ===========================================================================
extern "C" void kernel_launch(void* const* d_in, const int* in_sizes, int n_in,
                              void* d_out, int out_size) {
    const float* x     = (const float*)d_in[0];
    const int*   ei    = (const int*)d_in[1];
    const float* ea    = (const float*)d_in[2];
    const float* Wn    = (const float*)d_in[3];
    const float* bn    = (const float*)d_in[4];
    const float* We1   = (const float*)d_in[5];
    const float* be1   = (const float*)d_in[6];
    const float* We2   = (const float*)d_in[7];
    const float* be2   = (const float*)d_in[8];
    const float* Wroot = (const float*)d_in[9];
    const float* bconv = (const float*)d_in[10];
    const float* Wih   = (const float*)d_in[11];
    const float* Whh   = (const float*)d_in[12];
    const float* bih   = (const float*)d_in[13];
    const float* bhh   = (const float*)d_in[14];
    const int* src = ei;
    const int* dst = ei + EE;
    float* out = (float*)d_out;

    cudaFuncSetAttribute(k_wm_mma, cudaFuncAttributeMaxDynamicSharedMemorySize, SM_TOTAL);

    // edge network (once)
    k_edge_hidden<<<EE, 128>>>(ea, We1, be1);
    k_we2t<<<1024, 128>>>(We2);
    int mtiles = (EE + 127) / 128;   // 1172
    k_wm_mma<<<mtiles, 256, SM_TOTAL>>>(be2);

    // node init (+ agg zero)
    k_node_init<<<(NN * 32 + 255) / 256, 256>>>(x, Wn, bn);

    for (int s = 0; s < STEPS; s++) {
        k_message<<<(EE * 32 + 255) / 256, 256>>>(src, dst);
        int last = (s == STEPS - 1) ? 1 : 0;
        k_gru<<<(NN * 32 + 255) / 256, 256>>>(Wroot, bconv, Wih, Whh, bih, bhh,
                                              out, last);
    }
}

// round 6
// speedup vs baseline: 1.5410x; 1.0164x over previous
#include <cuda_runtime.h>
#include <cuda_bf16.h>
#include <cuda_fp16.h>
#include <cstdint>
#include <math.h>

#define NN 50000
#define EE 150000
#define NODE_IN 64
#define EDGE_IN 16
#define D 32
#define EH 128
#define STEPS 3

// Scratch (device globals — no allocation APIs allowed)
__device__ __nv_bfloat16 g_a_hi[(size_t)EE * EH];   // 38.4 MB
__device__ __nv_bfloat16 g_a_lo[(size_t)EE * EH];   // 38.4 MB
__device__ __nv_bfloat16 g_WT_hi[1024 * EH];        // We2^T hi, 256 KB
__device__ __nv_bfloat16 g_WT_lo[1024 * EH];        // We2^T lo, 256 KB
__device__ __half g_Wm_h[(size_t)EE * D * D];       // per-edge matrices, 307 MB (fp16)
__device__ float g_h[NN * D];                       // node state
__device__ float g_agg[NN * D];                     // scatter accumulator

// ===========================================================================
// K1: a_e = relu(edge_attr @ We1 + be1), emitted as bf16 hi/lo split
// ===========================================================================
__global__ void k_edge_hidden(const float* __restrict__ ea,
                              const float* __restrict__ We1,
                              const float* __restrict__ be1) {
    int e = blockIdx.x * 2 + (threadIdx.x >> 7);
    int t = threadIdx.x & 127;
    if (e >= EE) return;
    __shared__ float s_ea[2][EDGE_IN];
    if (t < EDGE_IN) s_ea[threadIdx.x >> 7][t] = ea[e * EDGE_IN + t];
    __syncthreads();
    const float* se = s_ea[threadIdx.x >> 7];
    float acc = be1[t];
#pragma unroll
    for (int i = 0; i < EDGE_IN; i++)
        acc = fmaf(se[i], We1[i * EH + t], acc);
    float a = fmaxf(acc, 0.0f);
    __nv_bfloat16 hi = __float2bfloat16(a);
    float lo = a - __bfloat162float(hi);
    g_a_hi[(size_t)e * EH + t] = hi;
    g_a_lo[(size_t)e * EH + t] = __float2bfloat16(lo);
}

// ===========================================================================
// K1b: We2^T hi/lo split:  WT[n][k] = We2[k][n]
// ===========================================================================
__global__ void k_we2t(const float* __restrict__ We2) {
    int n = blockIdx.x;             // 0..1023
    int k = threadIdx.x;            // 0..127
    float v = We2[(size_t)k * 1024 + n];
    __nv_bfloat16 hi = __float2bfloat16(v);
    float lo = v - __bfloat162float(hi);
    g_WT_hi[n * EH + k] = hi;
    g_WT_lo[n * EH + k] = __float2bfloat16(lo);
}

// ===========================================================================
// K2: Wm = a [E,128] @ We2 [128,1024] + be2, via mma.sync bf16 2-term split.
// CTA = 128 rows x 1024 cols (8 N-tiles of 128). 512 threads = 16 warps,
// warp grid 4x4, warp tile 32x32. ldmatrix fragment loads. fp16 output.
// ===========================================================================
#define APITCH 136                         // bf16 elems per smem row
#define TILE_BYTES (128 * APITCH * 2)      // 34816
#define OFF_A_HI 0
#define OFF_A_LO TILE_BYTES
#define OFF_B_HI (2 * TILE_BYTES)
#define OFF_B_LO (3 * TILE_BYTES)
#define SM_TOTAL (4 * TILE_BYTES)          // 139264

__device__ __forceinline__ uint32_t smem_u32(const void* p) {
    uint32_t a;
    asm("{ .reg .u64 t; cvta.to.shared.u64 t, %1; cvt.u32.u64 %0, t; }" : "=r"(a) : "l"(p));
    return a;
}
__device__ __forceinline__ void mma16816(float* c, const uint32_t* a, const uint32_t* b) {
    asm volatile(
        "mma.sync.aligned.m16n8k16.row.col.f32.bf16.bf16.f32 "
        "{%0,%1,%2,%3}, {%4,%5,%6,%7}, {%8,%9}, {%0,%1,%2,%3};"
        : "+f"(c[0]), "+f"(c[1]), "+f"(c[2]), "+f"(c[3])
        : "r"(a[0]), "r"(a[1]), "r"(a[2]), "r"(a[3]), "r"(b[0]), "r"(b[1]));
}
__device__ __forceinline__ void ldsm4(uint32_t* r, uint32_t addr) {
    asm volatile("ldmatrix.sync.aligned.m8n8.x4.shared.b16 {%0,%1,%2,%3}, [%4];"
        : "=r"(r[0]), "=r"(r[1]), "=r"(r[2]), "=r"(r[3]) : "r"(addr));
}

__global__ void __launch_bounds__(512, 1) k_wm_mma(const float* __restrict__ bias) {
    extern __shared__ char smem[];
    uint32_t sbase = smem_u32(smem);
    int tid = threadIdx.x;
    int wid = tid >> 5;
    int lane = tid & 31;
    int g = lane >> 2;          // group id (0..7)
    int tig = lane & 3;         // thread in group
    int wm = wid >> 2;          // 0..3 (32-row warp tile)
    int wn = wid & 3;           // 0..3 (32-col warp tile)
    int rowBase = blockIdx.x * 128;

    // ldmatrix per-lane address bases (element units within tile)
    // A x4: m0 rows0-7 k0-7, m1 rows8-15 k0-7, m2 rows0-7 k8-15, m3 rows8-15 k8-15
    int a_row = (lane & 7) + ((lane >> 3) & 1) * 8;
    int a_k   = ((lane >> 4) & 1) * 8;
    uint32_t aoff = (uint32_t)(((wm * 32 + a_row) * APITCH + a_k) * 2);
    // B x4: m0 n0-7 k0-7, m1 n0-7 k8-15, m2 n8-15 k0-7, m3 n8-15 k8-15
    int b_n = (lane & 7) + ((lane >> 4) & 1) * 8;
    int b_k = ((lane >> 3) & 1) * 8;
    uint32_t boff = (uint32_t)(((wn * 32 + b_n) * APITCH + b_k) * 2);

    // ---- stage A (hi/lo), 128 rows x 128 k, zero-pad past EE ----
    for (int idx = tid; idx < 2048; idx += 512) {   // 16B chunks
        int r = idx >> 4;
        int c = (idx & 15) * 8;
        int grow = rowBase + r;
        uint4 vh = make_uint4(0u, 0u, 0u, 0u), vl = vh;
        if (grow < EE) {
            vh = *(const uint4*)(g_a_hi + (size_t)grow * EH + c);
            vl = *(const uint4*)(g_a_lo + (size_t)grow * EH + c);
        }
        *(uint4*)(smem + OFF_A_HI + (r * APITCH + c) * 2) = vh;
        *(uint4*)(smem + OFF_A_LO + (r * APITCH + c) * 2) = vl;
    }

    for (int nt = 0; nt < 8; nt++) {
        int nBase = nt * 128;
        // ---- stage B tile [128 n-rows][128 k] hi/lo ----
        for (int idx = tid; idx < 2048; idx += 512) {
            int r = idx >> 4;
            int c = (idx & 15) * 8;
            *(uint4*)(smem + OFF_B_HI + (r * APITCH + c) * 2) =
                *(const uint4*)(g_WT_hi + (size_t)(nBase + r) * EH + c);
            *(uint4*)(smem + OFF_B_LO + (r * APITCH + c) * 2) =
                *(const uint4*)(g_WT_lo + (size_t)(nBase + r) * EH + c);
        }
        __syncthreads();

        float acc[2][4][4];
#pragma unroll
        for (int mi = 0; mi < 2; mi++)
#pragma unroll
            for (int ni = 0; ni < 4; ni++)
#pragma unroll
                for (int q = 0; q < 4; q++) acc[mi][ni][q] = 0.0f;

#pragma unroll
        for (int ks = 0; ks < 8; ks++) {
            uint32_t kb = (uint32_t)(ks * 32);   // k0*2 bytes
            uint32_t ah[2][4], al[2][4], bh[4][2], bl[4][2];
#pragma unroll
            for (int mi = 0; mi < 2; mi++) {
                uint32_t ao = aoff + (uint32_t)(mi * 16 * APITCH * 2) + kb;
                ldsm4(ah[mi], sbase + OFF_A_HI + ao);
                ldsm4(al[mi], sbase + OFF_A_LO + ao);
            }
#pragma unroll
            for (int nj = 0; nj < 2; nj++) {     // n16 blocks
                uint32_t bo = boff + (uint32_t)(nj * 16 * APITCH * 2) + kb;
                uint32_t th[4], tl[4];
                ldsm4(th, sbase + OFF_B_HI + bo);
                ldsm4(tl, sbase + OFF_B_LO + bo);
                bh[nj * 2][0] = th[0]; bh[nj * 2][1] = th[1];
                bh[nj * 2 + 1][0] = th[2]; bh[nj * 2 + 1][1] = th[3];
                bl[nj * 2][0] = tl[0]; bl[nj * 2][1] = tl[1];
                bl[nj * 2 + 1][0] = tl[2]; bl[nj * 2 + 1][1] = tl[3];
            }
#pragma unroll
            for (int mi = 0; mi < 2; mi++)
#pragma unroll
                for (int ni = 0; ni < 4; ni++) {
                    mma16816(acc[mi][ni], ah[mi], bh[ni]);
                    mma16816(acc[mi][ni], ah[mi], bl[ni]);
                    mma16816(acc[mi][ni], al[mi], bh[ni]);
                }
        }

        // ---- epilogue: +bias, cvt fp16, store ----
#pragma unroll
        for (int mi = 0; mi < 2; mi++) {
            int row0 = rowBase + wm * 32 + mi * 16 + g;
#pragma unroll
            for (int ni = 0; ni < 4; ni++) {
                int col = nBase + wn * 32 + ni * 8 + tig * 2;
                float b0 = __ldg(bias + col), b1 = __ldg(bias + col + 1);
                if (row0 < EE) {
                    __half2 v = __floats2half2_rn(acc[mi][ni][0] + b0, acc[mi][ni][1] + b1);
                    *(__half2*)(g_Wm_h + (size_t)row0 * 1024 + col) = v;
                }
                if (row0 + 8 < EE) {
                    __half2 v = __floats2half2_rn(acc[mi][ni][2] + b0, acc[mi][ni][3] + b1);
                    *(__half2*)(g_Wm_h + (size_t)(row0 + 8) * 1024 + col) = v;
                }
            }
        }
        __syncthreads();   // all frag loads done before B is overwritten
    }
}

// ===========================================================================
// K3: h = relu(x @ Wn + bn); zero g_agg
// ===========================================================================
__global__ void k_node_init(const float* __restrict__ x,
                            const float* __restrict__ Wn,
                            const float* __restrict__ bn) {
    int warp = (blockIdx.x * blockDim.x + threadIdx.x) >> 5;
    int lane = threadIdx.x & 31;
    if (warp >= NN) return;
    float x0 = x[warp * NODE_IN + lane];
    float x1 = x[warp * NODE_IN + 32 + lane];
    float acc = bn[lane];
#pragma unroll
    for (int i = 0; i < 32; i++) {
        acc = fmaf(__shfl_sync(0xffffffffu, x0, i), Wn[i * D + lane], acc);
        acc = fmaf(__shfl_sync(0xffffffffu, x1, i), Wn[(i + 32) * D + lane], acc);
    }
    g_h[warp * D + lane] = fmaxf(acc, 0.0f);
    g_agg[warp * D + lane] = 0.0f;
}

// ===========================================================================
// K5: per-edge m = h[src]^T Wm_e (fp16) ; atomicAdd into g_agg[dst]
// ===========================================================================
__global__ void k_message(const int* __restrict__ src, const int* __restrict__ dst) {
    int warp = (blockIdx.x * blockDim.x + threadIdx.x) >> 5;
    int lane = threadIdx.x & 31;
    if (warp >= EE) return;
    int s = src[warp];
    int d = dst[warp];
    float hv = g_h[s * D + lane];
    const __half* W = g_Wm_h + (size_t)warp * 1024;
    float m = 0.0f;
#pragma unroll
    for (int i = 0; i < 32; i++)
        m = fmaf(__shfl_sync(0xffffffffu, hv, i), __half2float(__ldg(W + i * D + lane)), m);
    atomicAdd(g_agg + d * D + lane, m);
}

// ===========================================================================
// K6: conv = relu(agg + h@Wroot + bconv); GRU(conv, h); re-zero agg
// ===========================================================================
__global__ void __launch_bounds__(256) k_gru(const float* __restrict__ Wroot,
                                             const float* __restrict__ bconv,
                                             const float* __restrict__ Wih,
                                             const float* __restrict__ Whh,
                                             const float* __restrict__ bih,
                                             const float* __restrict__ bhh,
                                             float* __restrict__ out_ext,
                                             int use_ext) {
    __shared__ float sWihT[32 * 96];
    __shared__ float sWhhT[32 * 96];
    int t = threadIdx.x;
    for (int idx = t; idx < 96 * 32; idx += blockDim.x) {
        int gg = idx / 32, i = idx % 32;
        sWihT[i * 96 + gg] = Wih[idx];
        sWhhT[i * 96 + gg] = Whh[idx];
    }
    __syncthreads();

    int warp = (blockIdx.x * blockDim.x + t) >> 5;
    int lane = t & 31;
    if (warp >= NN) return;

    float hv = g_h[warp * D + lane];
    float c = g_agg[warp * D + lane] + bconv[lane];
    g_agg[warp * D + lane] = 0.0f;
#pragma unroll
    for (int i = 0; i < 32; i++)
        c = fmaf(__shfl_sync(0xffffffffu, hv, i), Wroot[i * D + lane], c);
    c = fmaxf(c, 0.0f);

    float gr = bih[lane], gz = bih[32 + lane], gn = bih[64 + lane];
    float hr = bhh[lane], hz = bhh[32 + lane], hn = bhh[64 + lane];
#pragma unroll
    for (int i = 0; i < 32; i++) {
        float cv  = __shfl_sync(0xffffffffu, c, i);
        float hvi = __shfl_sync(0xffffffffu, hv, i);
        const float* wi = sWihT + i * 96;
        const float* wh = sWhhT + i * 96;
        gr = fmaf(cv, wi[lane], gr);
        gz = fmaf(cv, wi[32 + lane], gz);
        gn = fmaf(cv, wi[64 + lane], gn);
        hr = fmaf(hvi, wh[lane], hr);
        hz = fmaf(hvi, wh[32 + lane], hz);
        hn = fmaf(hvi, wh[64 + lane], hn);
    }
    float r  = 1.0f / (1.0f + expf(-(gr + hr)));
    float z  = 1.0f / (1.0f + expf(-(gz + hz)));
    float nn = tanhf(gn + r * hn);
    float hnew = (1.0f - z) * nn + z * hv;

    if (use_ext) out_ext[warp * D + lane] = hnew;
    else         g_h[warp * D + lane] = hnew;
}

// ===========================================================================
extern "C" void kernel_launch(void* const* d_in, const int* in_sizes, int n_in,
                              void* d_out, int out_size) {
    const float* x     = (const float*)d_in[0];
    const int*   ei    = (const int*)d_in[1];
    const float* ea    = (const float*)d_in[2];
    const float* Wn    = (const float*)d_in[3];
    const float* bn    = (const float*)d_in[4];
    const float* We1   = (const float*)d_in[5];
    const float* be1   = (const float*)d_in[6];
    const float* We2   = (const float*)d_in[7];
    const float* be2   = (const float*)d_in[8];
    const float* Wroot = (const float*)d_in[9];
    const float* bconv = (const float*)d_in[10];
    const float* Wih   = (const float*)d_in[11];
    const float* Whh   = (const float*)d_in[12];
    const float* bih   = (const float*)d_in[13];
    const float* bhh   = (const float*)d_in[14];
    const int* src = ei;
    const int* dst = ei + EE;
    float* out = (float*)d_out;

    cudaFuncSetAttribute(k_wm_mma, cudaFuncAttributeMaxDynamicSharedMemorySize, SM_TOTAL);

    // edge network (once)
    k_edge_hidden<<<(EE + 1) / 2, 256>>>(ea, We1, be1);
    k_we2t<<<1024, 128>>>(We2);
    int mtiles = (EE + 127) / 128;   // 1172
    k_wm_mma<<<mtiles, 512, SM_TOTAL>>>(be2);

    // node init (+ agg zero)
    k_node_init<<<(NN * 32 + 255) / 256, 256>>>(x, Wn, bn);

    for (int s = 0; s < STEPS; s++) {
        k_message<<<(EE * 32 + 255) / 256, 256>>>(src, dst);
        int last = (s == STEPS - 1) ? 1 : 0;
        k_gru<<<(NN * 32 + 255) / 256, 256>>>(Wroot, bconv, Wih, Whh, bih, bhh,
                                              out, last);
    }
}

// round 7
// speedup vs baseline: 1.8275x; 1.1859x over previous
#include <cuda_runtime.h>
#include <cuda_fp16.h>
#include <cstdint>
#include <math.h>

#define NN 50000
#define EE 150000
#define NODE_IN 64
#define EDGE_IN 16
#define D 32
#define EH 128
#define STEPS 3

// Scratch (device globals — no allocation APIs allowed)
__device__ __half g_a[(size_t)EE * EH];        // edge hidden (fp16), 38.4 MB
__device__ __half g_WT[1024 * EH];             // We2^T (fp16), 256 KB
__device__ __half g_Wm_h[(size_t)EE * D * D];  // per-edge matrices, 307 MB (fp16)
__device__ float g_h[NN * D];                  // node state
__device__ float g_agg[NN * D];                // scatter accumulator

// ===========================================================================
// K1: a_e = relu(edge_attr @ We1 + be1)  -> fp16
// ===========================================================================
__global__ void k_edge_hidden(const float* __restrict__ ea,
                              const float* __restrict__ We1,
                              const float* __restrict__ be1) {
    int e = blockIdx.x * 2 + (threadIdx.x >> 7);
    int t = threadIdx.x & 127;
    if (e >= EE) return;
    __shared__ float s_ea[2][EDGE_IN];
    if (t < EDGE_IN) s_ea[threadIdx.x >> 7][t] = ea[e * EDGE_IN + t];
    __syncthreads();
    const float* se = s_ea[threadIdx.x >> 7];
    float acc = be1[t];
#pragma unroll
    for (int i = 0; i < EDGE_IN; i++)
        acc = fmaf(se[i], We1[i * EH + t], acc);
    g_a[(size_t)e * EH + t] = __float2half_rn(fmaxf(acc, 0.0f));
}

// ===========================================================================
// K1b: We2^T -> fp16:  WT[n][k] = We2[k][n]
// ===========================================================================
__global__ void k_we2t(const float* __restrict__ We2) {
    int n = blockIdx.x;             // 0..1023
    int k = threadIdx.x;            // 0..127
    g_WT[n * EH + k] = __float2half_rn(We2[(size_t)k * 1024 + n]);
}

// ===========================================================================
// K2: Wm = a [E,128] @ We2 [128,1024] + be2, single-term fp16 mma.sync.
// CTA = 128 rows x 1024 cols (8 N-tiles of 128). 512 threads = 16 warps,
// warp grid 4x4, warp tile 32x32. ldmatrix fragment loads. fp16 output.
// ===========================================================================
#define APITCH 136                         // fp16 elems per smem row
#define TILE_BYTES (128 * APITCH * 2)      // 34816
#define OFF_A 0
#define OFF_B TILE_BYTES
#define SM_TOTAL (2 * TILE_BYTES)          // 69632 -> 2 CTAs/SM

__device__ __forceinline__ uint32_t smem_u32(const void* p) {
    uint32_t a;
    asm("{ .reg .u64 t; cvta.to.shared.u64 t, %1; cvt.u32.u64 %0, t; }" : "=r"(a) : "l"(p));
    return a;
}
__device__ __forceinline__ void mma16816(float* c, const uint32_t* a, const uint32_t* b) {
    asm volatile(
        "mma.sync.aligned.m16n8k16.row.col.f32.f16.f16.f32 "
        "{%0,%1,%2,%3}, {%4,%5,%6,%7}, {%8,%9}, {%0,%1,%2,%3};"
        : "+f"(c[0]), "+f"(c[1]), "+f"(c[2]), "+f"(c[3])
        : "r"(a[0]), "r"(a[1]), "r"(a[2]), "r"(a[3]), "r"(b[0]), "r"(b[1]));
}
__device__ __forceinline__ void ldsm4(uint32_t* r, uint32_t addr) {
    asm volatile("ldmatrix.sync.aligned.m8n8.x4.shared.b16 {%0,%1,%2,%3}, [%4];"
        : "=r"(r[0]), "=r"(r[1]), "=r"(r[2]), "=r"(r[3]) : "r"(addr));
}

__global__ void __launch_bounds__(512, 2) k_wm_mma(const float* __restrict__ bias) {
    extern __shared__ char smem[];
    uint32_t sbase = smem_u32(smem);
    int tid = threadIdx.x;
    int wid = tid >> 5;
    int lane = tid & 31;
    int g = lane >> 2;          // group id (0..7)
    int tig = lane & 3;         // thread in group
    int wm = wid >> 2;          // 0..3 (32-row warp tile)
    int wn = wid & 3;           // 0..3 (32-col warp tile)
    int rowBase = blockIdx.x * 128;

    // ldmatrix per-lane address bases
    int a_row = (lane & 7) + ((lane >> 3) & 1) * 8;
    int a_k   = ((lane >> 4) & 1) * 8;
    uint32_t aoff = (uint32_t)(((wm * 32 + a_row) * APITCH + a_k) * 2);
    int b_n = (lane & 7) + ((lane >> 4) & 1) * 8;
    int b_k = ((lane >> 3) & 1) * 8;
    uint32_t boff = (uint32_t)(((wn * 32 + b_n) * APITCH + b_k) * 2);

    // ---- stage A, 128 rows x 128 k, zero-pad past EE ----
    for (int idx = tid; idx < 2048; idx += 512) {   // 16B chunks
        int r = idx >> 4;
        int c = (idx & 15) * 8;
        int grow = rowBase + r;
        uint4 v = make_uint4(0u, 0u, 0u, 0u);
        if (grow < EE) v = *(const uint4*)(g_a + (size_t)grow * EH + c);
        *(uint4*)(smem + OFF_A + (r * APITCH + c) * 2) = v;
    }

    for (int nt = 0; nt < 8; nt++) {
        int nBase = nt * 128;
        // ---- stage B tile [128 n-rows][128 k] ----
        for (int idx = tid; idx < 2048; idx += 512) {
            int r = idx >> 4;
            int c = (idx & 15) * 8;
            *(uint4*)(smem + OFF_B + (r * APITCH + c) * 2) =
                *(const uint4*)(g_WT + (size_t)(nBase + r) * EH + c);
        }
        __syncthreads();

        float acc[2][4][4];
#pragma unroll
        for (int mi = 0; mi < 2; mi++)
#pragma unroll
            for (int ni = 0; ni < 4; ni++)
#pragma unroll
                for (int q = 0; q < 4; q++) acc[mi][ni][q] = 0.0f;

#pragma unroll
        for (int ks = 0; ks < 8; ks++) {
            uint32_t kb = (uint32_t)(ks * 32);   // k0*2 bytes
            uint32_t af[2][4], bf[4][2];
#pragma unroll
            for (int mi = 0; mi < 2; mi++)
                ldsm4(af[mi], sbase + OFF_A + aoff + (uint32_t)(mi * 16 * APITCH * 2) + kb);
#pragma unroll
            for (int nj = 0; nj < 2; nj++) {
                uint32_t tb[4];
                ldsm4(tb, sbase + OFF_B + boff + (uint32_t)(nj * 16 * APITCH * 2) + kb);
                bf[nj * 2][0] = tb[0]; bf[nj * 2][1] = tb[1];
                bf[nj * 2 + 1][0] = tb[2]; bf[nj * 2 + 1][1] = tb[3];
            }
#pragma unroll
            for (int mi = 0; mi < 2; mi++)
#pragma unroll
                for (int ni = 0; ni < 4; ni++)
                    mma16816(acc[mi][ni], af[mi], bf[ni]);
        }

        // ---- epilogue: +bias, cvt fp16, store ----
#pragma unroll
        for (int mi = 0; mi < 2; mi++) {
            int row0 = rowBase + wm * 32 + mi * 16 + g;
#pragma unroll
            for (int ni = 0; ni < 4; ni++) {
                int col = nBase + wn * 32 + ni * 8 + tig * 2;
                float b0 = __ldg(bias + col), b1 = __ldg(bias + col + 1);
                if (row0 < EE) {
                    __half2 v = __floats2half2_rn(acc[mi][ni][0] + b0, acc[mi][ni][1] + b1);
                    *(__half2*)(g_Wm_h + (size_t)row0 * 1024 + col) = v;
                }
                if (row0 + 8 < EE) {
                    __half2 v = __floats2half2_rn(acc[mi][ni][2] + b0, acc[mi][ni][3] + b1);
                    *(__half2*)(g_Wm_h + (size_t)(row0 + 8) * 1024 + col) = v;
                }
            }
        }
        __syncthreads();   // all frag loads done before B is overwritten
    }
}

// ===========================================================================
// K3: h = relu(x @ Wn + bn); zero g_agg
// ===========================================================================
__global__ void k_node_init(const float* __restrict__ x,
                            const float* __restrict__ Wn,
                            const float* __restrict__ bn) {
    int warp = (blockIdx.x * blockDim.x + threadIdx.x) >> 5;
    int lane = threadIdx.x & 31;
    if (warp >= NN) return;
    float x0 = x[warp * NODE_IN + lane];
    float x1 = x[warp * NODE_IN + 32 + lane];
    float acc = bn[lane];
#pragma unroll
    for (int i = 0; i < 32; i++) {
        acc = fmaf(__shfl_sync(0xffffffffu, x0, i), Wn[i * D + lane], acc);
        acc = fmaf(__shfl_sync(0xffffffffu, x1, i), Wn[(i + 32) * D + lane], acc);
    }
    g_h[warp * D + lane] = fmaxf(acc, 0.0f);
    g_agg[warp * D + lane] = 0.0f;
}

// ===========================================================================
// K5: per-edge m = h[src]^T Wm_e (fp16) ; atomicAdd into g_agg[dst]
// ===========================================================================
__global__ void k_message(const int* __restrict__ src, const int* __restrict__ dst) {
    int warp = (blockIdx.x * blockDim.x + threadIdx.x) >> 5;
    int lane = threadIdx.x & 31;
    if (warp >= EE) return;
    int s = src[warp];
    int d = dst[warp];
    float hv = g_h[s * D + lane];
    const __half* W = g_Wm_h + (size_t)warp * 1024;
    float m = 0.0f;
#pragma unroll
    for (int i = 0; i < 32; i++)
        m = fmaf(__shfl_sync(0xffffffffu, hv, i), __half2float(__ldg(W + i * D + lane)), m);
    atomicAdd(g_agg + d * D + lane, m);
}

// ===========================================================================
// K6: conv = relu(agg + h@Wroot + bconv); GRU(conv, h); re-zero agg
// ===========================================================================
__global__ void __launch_bounds__(256) k_gru(const float* __restrict__ Wroot,
                                             const float* __restrict__ bconv,
                                             const float* __restrict__ Wih,
                                             const float* __restrict__ Whh,
                                             const float* __restrict__ bih,
                                             const float* __restrict__ bhh,
                                             float* __restrict__ out_ext,
                                             int use_ext) {
    __shared__ float sWihT[32 * 96];
    __shared__ float sWhhT[32 * 96];
    int t = threadIdx.x;
    for (int idx = t; idx < 96 * 32; idx += blockDim.x) {
        int gg = idx / 32, i = idx % 32;
        sWihT[i * 96 + gg] = Wih[idx];
        sWhhT[i * 96 + gg] = Whh[idx];
    }
    __syncthreads();

    int warp = (blockIdx.x * blockDim.x + t) >> 5;
    int lane = t & 31;
    if (warp >= NN) return;

    float hv = g_h[warp * D + lane];
    float c = g_agg[warp * D + lane] + bconv[lane];
    g_agg[warp * D + lane] = 0.0f;
#pragma unroll
    for (int i = 0; i < 32; i++)
        c = fmaf(__shfl_sync(0xffffffffu, hv, i), Wroot[i * D + lane], c);
    c = fmaxf(c, 0.0f);

    float gr = bih[lane], gz = bih[32 + lane], gn = bih[64 + lane];
    float hr = bhh[lane], hz = bhh[32 + lane], hn = bhh[64 + lane];
#pragma unroll
    for (int i = 0; i < 32; i++) {
        float cv  = __shfl_sync(0xffffffffu, c, i);
        float hvi = __shfl_sync(0xffffffffu, hv, i);
        const float* wi = sWihT + i * 96;
        const float* wh = sWhhT + i * 96;
        gr = fmaf(cv, wi[lane], gr);
        gz = fmaf(cv, wi[32 + lane], gz);
        gn = fmaf(cv, wi[64 + lane], gn);
        hr = fmaf(hvi, wh[lane], hr);
        hz = fmaf(hvi, wh[32 + lane], hz);
        hn = fmaf(hvi, wh[64 + lane], hn);
    }
    float r  = 1.0f / (1.0f + expf(-(gr + hr)));
    float z  = 1.0f / (1.0f + expf(-(gz + hz)));
    float nn = tanhf(gn + r * hn);
    float hnew = (1.0f - z) * nn + z * hv;

    if (use_ext) out_ext[warp * D + lane] = hnew;
    else         g_h[warp * D + lane] = hnew;
}

// ===========================================================================
extern "C" void kernel_launch(void* const* d_in, const int* in_sizes, int n_in,
                              void* d_out, int out_size) {
    const float* x     = (const float*)d_in[0];
    const int*   ei    = (const int*)d_in[1];
    const float* ea    = (const float*)d_in[2];
    const float* Wn    = (const float*)d_in[3];
    const float* bn    = (const float*)d_in[4];
    const float* We1   = (const float*)d_in[5];
    const float* be1   = (const float*)d_in[6];
    const float* We2   = (const float*)d_in[7];
    const float* be2   = (const float*)d_in[8];
    const float* Wroot = (const float*)d_in[9];
    const float* bconv = (const float*)d_in[10];
    const float* Wih   = (const float*)d_in[11];
    const float* Whh   = (const float*)d_in[12];
    const float* bih   = (const float*)d_in[13];
    const float* bhh   = (const float*)d_in[14];
    const int* src = ei;
    const int* dst = ei + EE;
    float* out = (float*)d_out;

    cudaFuncSetAttribute(k_wm_mma, cudaFuncAttributeMaxDynamicSharedMemorySize, SM_TOTAL);

    // edge network (once)
    k_edge_hidden<<<(EE + 1) / 2, 256>>>(ea, We1, be1);
    k_we2t<<<1024, 128>>>(We2);
    int mtiles = (EE + 127) / 128;   // 1172
    k_wm_mma<<<mtiles, 512, SM_TOTAL>>>(be2);

    // node init (+ agg zero)
    k_node_init<<<(NN * 32 + 255) / 256, 256>>>(x, Wn, bn);

    for (int s = 0; s < STEPS; s++) {
        k_message<<<(EE * 32 + 255) / 256, 256>>>(src, dst);
        int last = (s == STEPS - 1) ? 1 : 0;
        k_gru<<<(NN * 32 + 255) / 256, 256>>>(Wroot, bconv, Wih, Whh, bih, bhh,
                                              out, last);
    }
}

// round 8
// speedup vs baseline: 1.8355x; 1.0043x over previous
#include <cuda_runtime.h>
#include <cuda_fp16.h>
#include <cstdint>
#include <math.h>

#define NN 50000
#define EE 150000
#define NODE_IN 64
#define EDGE_IN 16
#define D 32
#define EH 128
#define STEPS 3

// Scratch (device globals — no allocation APIs allowed)
__device__ __half g_a[(size_t)EE * EH];        // edge hidden (fp16), 38.4 MB
__device__ __half g_WT[1024 * EH];             // We2^T (fp16), 256 KB
__device__ __half g_Wm_h[(size_t)EE * D * D];  // per-edge matrices, 307 MB (fp16)
__device__ float g_h[NN * D];                  // node state
__device__ float g_agg[NN * D];                // scatter accumulator

// ===========================================================================
// K1: a_e = relu(edge_attr @ We1 + be1)  -> fp16
// ===========================================================================
__global__ void k_edge_hidden(const float* __restrict__ ea,
                              const float* __restrict__ We1,
                              const float* __restrict__ be1) {
    int e = blockIdx.x * 2 + (threadIdx.x >> 7);
    int t = threadIdx.x & 127;
    if (e >= EE) return;
    __shared__ float s_ea[2][EDGE_IN];
    if (t < EDGE_IN) s_ea[threadIdx.x >> 7][t] = ea[e * EDGE_IN + t];
    __syncthreads();
    const float* se = s_ea[threadIdx.x >> 7];
    float acc = be1[t];
#pragma unroll
    for (int i = 0; i < EDGE_IN; i++)
        acc = fmaf(se[i], We1[i * EH + t], acc);
    g_a[(size_t)e * EH + t] = __float2half_rn(fmaxf(acc, 0.0f));
}

// ===========================================================================
// K1b: We2^T -> fp16:  WT[n][k] = We2[k][n]
// ===========================================================================
__global__ void k_we2t(const float* __restrict__ We2) {
    int n = blockIdx.x;             // 0..1023
    int k = threadIdx.x;            // 0..127
    g_WT[n * EH + k] = __float2half_rn(We2[(size_t)k * 1024 + n]);
}

// ===========================================================================
// K2: Wm = a [E,128] @ We2 [128,1024] + be2, fp16 mma.sync.
// CTA = 128 rows x 1024 cols (8 N-tiles of 128). 256 threads = 8 warps,
// warp grid 2x4, warp tile 64x32. 2 CTAs/SM, 128 regs/thread (no spills).
// ===========================================================================
#define APITCH 136                         // fp16 elems per smem row
#define TILE_BYTES (128 * APITCH * 2)      // 34816
#define OFF_BIAS 0
#define OFF_A 4096
#define OFF_B (OFF_A + TILE_BYTES)
#define SM_TOTAL (OFF_B + TILE_BYTES)      // 73728 -> 2 CTAs/SM

__device__ __forceinline__ uint32_t smem_u32(const void* p) {
    uint32_t a;
    asm("{ .reg .u64 t; cvta.to.shared.u64 t, %1; cvt.u32.u64 %0, t; }" : "=r"(a) : "l"(p));
    return a;
}
__device__ __forceinline__ void mma16816(float* c, const uint32_t* a, const uint32_t* b) {
    asm volatile(
        "mma.sync.aligned.m16n8k16.row.col.f32.f16.f16.f32 "
        "{%0,%1,%2,%3}, {%4,%5,%6,%7}, {%8,%9}, {%0,%1,%2,%3};"
        : "+f"(c[0]), "+f"(c[1]), "+f"(c[2]), "+f"(c[3])
        : "r"(a[0]), "r"(a[1]), "r"(a[2]), "r"(a[3]), "r"(b[0]), "r"(b[1]));
}
__device__ __forceinline__ void ldsm4(uint32_t* r, uint32_t addr) {
    asm volatile("ldmatrix.sync.aligned.m8n8.x4.shared.b16 {%0,%1,%2,%3}, [%4];"
        : "=r"(r[0]), "=r"(r[1]), "=r"(r[2]), "=r"(r[3]) : "r"(addr));
}

__global__ void __launch_bounds__(256, 2) k_wm_mma(const float* __restrict__ bias) {
    extern __shared__ char smem[];
    uint32_t sbase = smem_u32(smem);
    float* sbias = (float*)(smem + OFF_BIAS);
    int tid = threadIdx.x;
    int wid = tid >> 5;
    int lane = tid & 31;
    int g = lane >> 2;          // group id (0..7)
    int tig = lane & 3;         // thread in group
    int wm = wid >> 2;          // 0..1 (64-row warp tile)
    int wn = wid & 3;           // 0..3 (32-col warp tile)
    int rowBase = blockIdx.x * 128;

    for (int i = tid; i < 1024; i += 256) sbias[i] = bias[i];

    // ldmatrix per-lane address bases
    int a_row = (lane & 7) + ((lane >> 3) & 1) * 8;
    int a_k   = ((lane >> 4) & 1) * 8;
    uint32_t aoff = (uint32_t)(((wm * 64 + a_row) * APITCH + a_k) * 2);
    int b_n = (lane & 7) + ((lane >> 4) & 1) * 8;
    int b_k = ((lane >> 3) & 1) * 8;
    uint32_t boff = (uint32_t)(((wn * 32 + b_n) * APITCH + b_k) * 2);

    // ---- stage A, 128 rows x 128 k, zero-pad past EE ----
    for (int idx = tid; idx < 2048; idx += 256) {   // 16B chunks
        int r = idx >> 4;
        int c = (idx & 15) * 8;
        int grow = rowBase + r;
        uint4 v = make_uint4(0u, 0u, 0u, 0u);
        if (grow < EE) v = *(const uint4*)(g_a + (size_t)grow * EH + c);
        *(uint4*)(smem + OFF_A + (r * APITCH + c) * 2) = v;
    }

    for (int nt = 0; nt < 8; nt++) {
        int nBase = nt * 128;
        // ---- stage B tile [128 n-rows][128 k] ----
        for (int idx = tid; idx < 2048; idx += 256) {
            int r = idx >> 4;
            int c = (idx & 15) * 8;
            *(uint4*)(smem + OFF_B + (r * APITCH + c) * 2) =
                *(const uint4*)(g_WT + (size_t)(nBase + r) * EH + c);
        }
        __syncthreads();

        float acc[4][4][4];
#pragma unroll
        for (int mi = 0; mi < 4; mi++)
#pragma unroll
            for (int ni = 0; ni < 4; ni++)
#pragma unroll
                for (int q = 0; q < 4; q++) acc[mi][ni][q] = 0.0f;

#pragma unroll
        for (int ks = 0; ks < 8; ks++) {
            uint32_t kb = (uint32_t)(ks * 32);   // k0*2 bytes
            uint32_t af[4][4], bf[4][2];
#pragma unroll
            for (int mi = 0; mi < 4; mi++)
                ldsm4(af[mi], sbase + OFF_A + aoff + (uint32_t)(mi * 16 * APITCH * 2) + kb);
#pragma unroll
            for (int nj = 0; nj < 2; nj++) {
                uint32_t tb[4];
                ldsm4(tb, sbase + OFF_B + boff + (uint32_t)(nj * 16 * APITCH * 2) + kb);
                bf[nj * 2][0] = tb[0]; bf[nj * 2][1] = tb[1];
                bf[nj * 2 + 1][0] = tb[2]; bf[nj * 2 + 1][1] = tb[3];
            }
#pragma unroll
            for (int mi = 0; mi < 4; mi++)
#pragma unroll
                for (int ni = 0; ni < 4; ni++)
                    mma16816(acc[mi][ni], af[mi], bf[ni]);
        }

        // ---- epilogue: +bias (smem), cvt fp16, store ----
#pragma unroll
        for (int mi = 0; mi < 4; mi++) {
            int row0 = rowBase + wm * 64 + mi * 16 + g;
#pragma unroll
            for (int ni = 0; ni < 4; ni++) {
                int col = nBase + wn * 32 + ni * 8 + tig * 2;
                float b0 = sbias[col], b1 = sbias[col + 1];
                if (row0 < EE) {
                    __half2 v = __floats2half2_rn(acc[mi][ni][0] + b0, acc[mi][ni][1] + b1);
                    *(__half2*)(g_Wm_h + (size_t)row0 * 1024 + col) = v;
                }
                if (row0 + 8 < EE) {
                    __half2 v = __floats2half2_rn(acc[mi][ni][2] + b0, acc[mi][ni][3] + b1);
                    *(__half2*)(g_Wm_h + (size_t)(row0 + 8) * 1024 + col) = v;
                }
            }
        }
        __syncthreads();   // all frag loads done before B is overwritten
    }
}

// ===========================================================================
// K3: h = relu(x @ Wn + bn); zero g_agg
// ===========================================================================
__global__ void k_node_init(const float* __restrict__ x,
                            const float* __restrict__ Wn,
                            const float* __restrict__ bn) {
    int warp = (blockIdx.x * blockDim.x + threadIdx.x) >> 5;
    int lane = threadIdx.x & 31;
    if (warp >= NN) return;
    float x0 = x[warp * NODE_IN + lane];
    float x1 = x[warp * NODE_IN + 32 + lane];
    float acc = bn[lane];
#pragma unroll
    for (int i = 0; i < 32; i++) {
        acc = fmaf(__shfl_sync(0xffffffffu, x0, i), Wn[i * D + lane], acc);
        acc = fmaf(__shfl_sync(0xffffffffu, x1, i), Wn[(i + 32) * D + lane], acc);
    }
    g_h[warp * D + lane] = fmaxf(acc, 0.0f);
    g_agg[warp * D + lane] = 0.0f;
}

// ===========================================================================
// K5: per-edge m = h[src]^T Wm_e (fp16) ; atomicAdd into g_agg[dst]
// ===========================================================================
__global__ void k_message(const int* __restrict__ src, const int* __restrict__ dst) {
    int warp = (blockIdx.x * blockDim.x + threadIdx.x) >> 5;
    int lane = threadIdx.x & 31;
    if (warp >= EE) return;
    int s = src[warp];
    int d = dst[warp];
    float hv = g_h[s * D + lane];
    const __half* W = g_Wm_h + (size_t)warp * 1024;
    float m = 0.0f;
#pragma unroll
    for (int i = 0; i < 32; i++)
        m = fmaf(__shfl_sync(0xffffffffu, hv, i), __half2float(__ldg(W + i * D + lane)), m);
    atomicAdd(g_agg + d * D + lane, m);
}

// ===========================================================================
// K6: conv = relu(agg + h@Wroot + bconv); GRU(conv, h); re-zero agg
// ===========================================================================
__global__ void __launch_bounds__(256) k_gru(const float* __restrict__ Wroot,
                                             const float* __restrict__ bconv,
                                             const float* __restrict__ Wih,
                                             const float* __restrict__ Whh,
                                             const float* __restrict__ bih,
                                             const float* __restrict__ bhh,
                                             float* __restrict__ out_ext,
                                             int use_ext) {
    __shared__ float sWihT[32 * 96];
    __shared__ float sWhhT[32 * 96];
    int t = threadIdx.x;
    for (int idx = t; idx < 96 * 32; idx += blockDim.x) {
        int gg = idx / 32, i = idx % 32;
        sWihT[i * 96 + gg] = Wih[idx];
        sWhhT[i * 96 + gg] = Whh[idx];
    }
    __syncthreads();

    int warp = (blockIdx.x * blockDim.x + t) >> 5;
    int lane = t & 31;
    if (warp >= NN) return;

    float hv = g_h[warp * D + lane];
    float c = g_agg[warp * D + lane] + bconv[lane];
    g_agg[warp * D + lane] = 0.0f;
#pragma unroll
    for (int i = 0; i < 32; i++)
        c = fmaf(__shfl_sync(0xffffffffu, hv, i), Wroot[i * D + lane], c);
    c = fmaxf(c, 0.0f);

    float gr = bih[lane], gz = bih[32 + lane], gn = bih[64 + lane];
    float hr = bhh[lane], hz = bhh[32 + lane], hn = bhh[64 + lane];
#pragma unroll
    for (int i = 0; i < 32; i++) {
        float cv  = __shfl_sync(0xffffffffu, c, i);
        float hvi = __shfl_sync(0xffffffffu, hv, i);
        const float* wi = sWihT + i * 96;
        const float* wh = sWhhT + i * 96;
        gr = fmaf(cv, wi[lane], gr);
        gz = fmaf(cv, wi[32 + lane], gz);
        gn = fmaf(cv, wi[64 + lane], gn);
        hr = fmaf(hvi, wh[lane], hr);
        hz = fmaf(hvi, wh[32 + lane], hz);
        hn = fmaf(hvi, wh[64 + lane], hn);
    }
    float r  = 1.0f / (1.0f + expf(-(gr + hr)));
    float z  = 1.0f / (1.0f + expf(-(gz + hz)));
    float nn = tanhf(gn + r * hn);
    float hnew = (1.0f - z) * nn + z * hv;

    if (use_ext) out_ext[warp * D + lane] = hnew;
    else         g_h[warp * D + lane] = hnew;
}

// ===========================================================================
extern "C" void kernel_launch(void* const* d_in, const int* in_sizes, int n_in,
                              void* d_out, int out_size) {
    const float* x     = (const float*)d_in[0];
    const int*   ei    = (const int*)d_in[1];
    const float* ea    = (const float*)d_in[2];
    const float* Wn    = (const float*)d_in[3];
    const float* bn    = (const float*)d_in[4];
    const float* We1   = (const float*)d_in[5];
    const float* be1   = (const float*)d_in[6];
    const float* We2   = (const float*)d_in[7];
    const float* be2   = (const float*)d_in[8];
    const float* Wroot = (const float*)d_in[9];
    const float* bconv = (const float*)d_in[10];
    const float* Wih   = (const float*)d_in[11];
    const float* Whh   = (const float*)d_in[12];
    const float* bih   = (const float*)d_in[13];
    const float* bhh   = (const float*)d_in[14];
    const int* src = ei;
    const int* dst = ei + EE;
    float* out = (float*)d_out;

    cudaFuncSetAttribute(k_wm_mma, cudaFuncAttributeMaxDynamicSharedMemorySize, SM_TOTAL);

    // edge network (once)
    k_edge_hidden<<<(EE + 1) / 2, 256>>>(ea, We1, be1);
    k_we2t<<<1024, 128>>>(We2);
    int mtiles = (EE + 127) / 128;   // 1172
    k_wm_mma<<<mtiles, 256, SM_TOTAL>>>(be2);

    // node init (+ agg zero)
    k_node_init<<<(NN * 32 + 255) / 256, 256>>>(x, Wn, bn);

    for (int s = 0; s < STEPS; s++) {
        k_message<<<(EE * 32 + 255) / 256, 256>>>(src, dst);
        int last = (s == STEPS - 1) ? 1 : 0;
        k_gru<<<(NN * 32 + 255) / 256, 256>>>(Wroot, bconv, Wih, Whh, bih, bhh,
                                              out, last);
    }
}

// round 9
// speedup vs baseline: 1.8679x; 1.0177x over previous
#include <cuda_runtime.h>
#include <cuda_fp16.h>
#include <cstdint>
#include <math.h>

#define NN 50000
#define EE 150000
#define NODE_IN 64
#define EDGE_IN 16
#define D 32
#define EH 128
#define STEPS 3

// Scratch (device globals — no allocation APIs allowed)
__device__ __half g_a[(size_t)EE * EH];        // edge hidden (fp16), 38.4 MB
__device__ __half g_WT[1024 * EH];             // We2^T (fp16), 256 KB
__device__ __half g_Wm_h[(size_t)EE * D * D];  // per-edge matrices, 307 MB (fp16)
__device__ float g_h[NN * D];                  // node state
__device__ float g_agg[NN * D];                // scatter accumulator

// ===========================================================================
// K1: a_e = relu(edge_attr @ We1 + be1)  -> fp16
// ===========================================================================
__global__ void k_edge_hidden(const float* __restrict__ ea,
                              const float* __restrict__ We1,
                              const float* __restrict__ be1) {
    int e = blockIdx.x * 2 + (threadIdx.x >> 7);
    int t = threadIdx.x & 127;
    if (e >= EE) return;
    __shared__ float s_ea[2][EDGE_IN];
    if (t < EDGE_IN) s_ea[threadIdx.x >> 7][t] = ea[e * EDGE_IN + t];
    __syncthreads();
    const float* se = s_ea[threadIdx.x >> 7];
    float acc = be1[t];
#pragma unroll
    for (int i = 0; i < EDGE_IN; i++)
        acc = fmaf(se[i], We1[i * EH + t], acc);
    g_a[(size_t)e * EH + t] = __float2half_rn(fmaxf(acc, 0.0f));
}

// ===========================================================================
// K1b: We2^T -> fp16:  WT[n][k] = We2[k][n]
// ===========================================================================
__global__ void k_we2t(const float* __restrict__ We2) {
    int n = blockIdx.x;             // 0..1023
    int k = threadIdx.x;            // 0..127
    g_WT[n * EH + k] = __float2half_rn(We2[(size_t)k * 1024 + n]);
}

// ===========================================================================
// K2: Wm = a [E,128] @ We2 [128,1024] + be2, fp16 mma.sync.
// CTA = 128 rows x 1024 cols (8 N-tiles of 128). 256 threads = 8 warps,
// warp grid 2x4, warp tile 64x32. 2 CTAs/SM. cp.async double-buffered B.
// ===========================================================================
#define APITCH 136                         // fp16 elems per smem row
#define TILE_BYTES (128 * APITCH * 2)      // 34816
#define OFF_BIAS 0
#define OFF_A 4096
#define OFF_B0 (OFF_A + TILE_BYTES)
#define OFF_B1 (OFF_B0 + TILE_BYTES)
#define SM_TOTAL (OFF_B1 + TILE_BYTES)     // 108544 -> 2 CTAs/SM

__device__ __forceinline__ uint32_t smem_u32(const void* p) {
    uint32_t a;
    asm("{ .reg .u64 t; cvta.to.shared.u64 t, %1; cvt.u32.u64 %0, t; }" : "=r"(a) : "l"(p));
    return a;
}
__device__ __forceinline__ void mma16816(float* c, const uint32_t* a, const uint32_t* b) {
    asm volatile(
        "mma.sync.aligned.m16n8k16.row.col.f32.f16.f16.f32 "
        "{%0,%1,%2,%3}, {%4,%5,%6,%7}, {%8,%9}, {%0,%1,%2,%3};"
        : "+f"(c[0]), "+f"(c[1]), "+f"(c[2]), "+f"(c[3])
        : "r"(a[0]), "r"(a[1]), "r"(a[2]), "r"(a[3]), "r"(b[0]), "r"(b[1]));
}
__device__ __forceinline__ void ldsm4(uint32_t* r, uint32_t addr) {
    asm volatile("ldmatrix.sync.aligned.m8n8.x4.shared.b16 {%0,%1,%2,%3}, [%4];"
        : "=r"(r[0]), "=r"(r[1]), "=r"(r[2]), "=r"(r[3]) : "r"(addr));
}
__device__ __forceinline__ void cp_async16(uint32_t dst, const void* src) {
    asm volatile("cp.async.cg.shared.global [%0], [%1], 16;" :: "r"(dst), "l"(src));
}

__global__ void __launch_bounds__(256, 2) k_wm_mma(const float* __restrict__ bias) {
    extern __shared__ char smem[];
    uint32_t sbase = smem_u32(smem);
    float* sbias = (float*)(smem + OFF_BIAS);
    int tid = threadIdx.x;
    int wid = tid >> 5;
    int lane = tid & 31;
    int g = lane >> 2;          // group id (0..7)
    int tig = lane & 3;         // thread in group
    int wm = wid >> 2;          // 0..1 (64-row warp tile)
    int wn = wid & 3;           // 0..3 (32-col warp tile)
    int rowBase = blockIdx.x * 128;

    // staging index for this thread (8 chunks of 16B per tile)
    // chunk idx -> r = idx>>4, c = (idx&15)*8
    // prefetch B(0) first so it overlaps A staging
    {
        for (int idx = tid; idx < 2048; idx += 256) {
            int r = idx >> 4;
            int c = (idx & 15) * 8;
            cp_async16(sbase + OFF_B0 + (uint32_t)((r * APITCH + c) * 2),
                       g_WT + (size_t)r * EH + c);
        }
        asm volatile("cp.async.commit_group;");
    }

    for (int i = tid; i < 1024; i += 256) sbias[i] = bias[i];

    // ---- stage A, 128 rows x 128 k, zero-pad past EE ----
    for (int idx = tid; idx < 2048; idx += 256) {
        int r = idx >> 4;
        int c = (idx & 15) * 8;
        int grow = rowBase + r;
        uint4 v = make_uint4(0u, 0u, 0u, 0u);
        if (grow < EE) v = *(const uint4*)(g_a + (size_t)grow * EH + c);
        *(uint4*)(smem + OFF_A + (r * APITCH + c) * 2) = v;
    }

    // ldmatrix per-lane address bases
    int a_row = (lane & 7) + ((lane >> 3) & 1) * 8;
    int a_k   = ((lane >> 4) & 1) * 8;
    uint32_t aoff = (uint32_t)(((wm * 64 + a_row) * APITCH + a_k) * 2);
    int b_n = (lane & 7) + ((lane >> 4) & 1) * 8;
    int b_k = ((lane >> 3) & 1) * 8;
    uint32_t boff = (uint32_t)(((wn * 32 + b_n) * APITCH + b_k) * 2);

    for (int nt = 0; nt < 8; nt++) {
        uint32_t curB = (nt & 1) ? OFF_B1 : OFF_B0;
        uint32_t nxtB = (nt & 1) ? OFF_B0 : OFF_B1;

        asm volatile("cp.async.wait_group 0;");
        __syncthreads();   // B(nt) visible to all; all warps done reading the buffer we now refill

        if (nt < 7) {
            int nBase = (nt + 1) * 128;
            for (int idx = tid; idx < 2048; idx += 256) {
                int r = idx >> 4;
                int c = (idx & 15) * 8;
                cp_async16(sbase + nxtB + (uint32_t)((r * APITCH + c) * 2),
                           g_WT + (size_t)(nBase + r) * EH + c);
            }
            asm volatile("cp.async.commit_group;");
        }

        float acc[4][4][4];
#pragma unroll
        for (int mi = 0; mi < 4; mi++)
#pragma unroll
            for (int ni = 0; ni < 4; ni++)
#pragma unroll
                for (int q = 0; q < 4; q++) acc[mi][ni][q] = 0.0f;

#pragma unroll
        for (int ks = 0; ks < 8; ks++) {
            uint32_t kb = (uint32_t)(ks * 32);   // k0*2 bytes
            uint32_t af[4][4], bf[4][2];
#pragma unroll
            for (int mi = 0; mi < 4; mi++)
                ldsm4(af[mi], sbase + OFF_A + aoff + (uint32_t)(mi * 16 * APITCH * 2) + kb);
#pragma unroll
            for (int nj = 0; nj < 2; nj++) {
                uint32_t tb[4];
                ldsm4(tb, sbase + curB + boff + (uint32_t)(nj * 16 * APITCH * 2) + kb);
                bf[nj * 2][0] = tb[0]; bf[nj * 2][1] = tb[1];
                bf[nj * 2 + 1][0] = tb[2]; bf[nj * 2 + 1][1] = tb[3];
            }
#pragma unroll
            for (int mi = 0; mi < 4; mi++)
#pragma unroll
                for (int ni = 0; ni < 4; ni++)
                    mma16816(acc[mi][ni], af[mi], bf[ni]);
        }

        // ---- epilogue: +bias (smem), cvt fp16, store ----
        int nBase = nt * 128;
#pragma unroll
        for (int mi = 0; mi < 4; mi++) {
            int row0 = rowBase + wm * 64 + mi * 16 + g;
#pragma unroll
            for (int ni = 0; ni < 4; ni++) {
                int col = nBase + wn * 32 + ni * 8 + tig * 2;
                float b0 = sbias[col], b1 = sbias[col + 1];
                if (row0 < EE) {
                    __half2 v = __floats2half2_rn(acc[mi][ni][0] + b0, acc[mi][ni][1] + b1);
                    *(__half2*)(g_Wm_h + (size_t)row0 * 1024 + col) = v;
                }
                if (row0 + 8 < EE) {
                    __half2 v = __floats2half2_rn(acc[mi][ni][2] + b0, acc[mi][ni][3] + b1);
                    *(__half2*)(g_Wm_h + (size_t)(row0 + 8) * 1024 + col) = v;
                }
            }
        }
        // no trailing barrier: top-of-loop wait+sync protects buffer reuse
    }
}

// ===========================================================================
// K3: h = relu(x @ Wn + bn); zero g_agg
// ===========================================================================
__global__ void k_node_init(const float* __restrict__ x,
                            const float* __restrict__ Wn,
                            const float* __restrict__ bn) {
    int warp = (blockIdx.x * blockDim.x + threadIdx.x) >> 5;
    int lane = threadIdx.x & 31;
    if (warp >= NN) return;
    float x0 = x[warp * NODE_IN + lane];
    float x1 = x[warp * NODE_IN + 32 + lane];
    float acc = bn[lane];
#pragma unroll
    for (int i = 0; i < 32; i++) {
        acc = fmaf(__shfl_sync(0xffffffffu, x0, i), Wn[i * D + lane], acc);
        acc = fmaf(__shfl_sync(0xffffffffu, x1, i), Wn[(i + 32) * D + lane], acc);
    }
    g_h[warp * D + lane] = fmaxf(acc, 0.0f);
    g_agg[warp * D + lane] = 0.0f;
}

// ===========================================================================
// K5: per-edge m = h[src]^T Wm_e (fp16) ; atomicAdd into g_agg[dst]
// ===========================================================================
__global__ void k_message(const int* __restrict__ src, const int* __restrict__ dst) {
    int warp = (blockIdx.x * blockDim.x + threadIdx.x) >> 5;
    int lane = threadIdx.x & 31;
    if (warp >= EE) return;
    int s = src[warp];
    int d = dst[warp];
    float hv = g_h[s * D + lane];
    const __half* W = g_Wm_h + (size_t)warp * 1024;
    float m = 0.0f;
#pragma unroll
    for (int i = 0; i < 32; i++)
        m = fmaf(__shfl_sync(0xffffffffu, hv, i), __half2float(__ldg(W + i * D + lane)), m);
    atomicAdd(g_agg + d * D + lane, m);
}

// ===========================================================================
// K6: conv = relu(agg + h@Wroot + bconv); GRU(conv, h); re-zero agg
// ===========================================================================
__global__ void __launch_bounds__(256) k_gru(const float* __restrict__ Wroot,
                                             const float* __restrict__ bconv,
                                             const float* __restrict__ Wih,
                                             const float* __restrict__ Whh,
                                             const float* __restrict__ bih,
                                             const float* __restrict__ bhh,
                                             float* __restrict__ out_ext,
                                             int use_ext) {
    __shared__ float sWihT[32 * 96];
    __shared__ float sWhhT[32 * 96];
    int t = threadIdx.x;
    // conflict-free transpose: adjacent threads write adjacent smem addrs
    for (int idx = t; idx < 96 * 32; idx += blockDim.x) {
        int i = idx / 96, gg = idx % 96;      // dst = i*96+gg (contiguous)
        sWihT[idx] = Wih[gg * 32 + i];
        sWhhT[idx] = Whh[gg * 32 + i];
    }
    __syncthreads();

    int warp = (blockIdx.x * blockDim.x + t) >> 5;
    int lane = t & 31;
    if (warp >= NN) return;

    float hv = g_h[warp * D + lane];
    float c = g_agg[warp * D + lane] + bconv[lane];
    g_agg[warp * D + lane] = 0.0f;
#pragma unroll
    for (int i = 0; i < 32; i++)
        c = fmaf(__shfl_sync(0xffffffffu, hv, i), Wroot[i * D + lane], c);
    c = fmaxf(c, 0.0f);

    float gr = bih[lane], gz = bih[32 + lane], gn = bih[64 + lane];
    float hr = bhh[lane], hz = bhh[32 + lane], hn = bhh[64 + lane];
#pragma unroll
    for (int i = 0; i < 32; i++) {
        float cv  = __shfl_sync(0xffffffffu, c, i);
        float hvi = __shfl_sync(0xffffffffu, hv, i);
        const float* wi = sWihT + i * 96;
        const float* wh = sWhhT + i * 96;
        gr = fmaf(cv, wi[lane], gr);
        gz = fmaf(cv, wi[32 + lane], gz);
        gn = fmaf(cv, wi[64 + lane], gn);
        hr = fmaf(hvi, wh[lane], hr);
        hz = fmaf(hvi, wh[32 + lane], hz);
        hn = fmaf(hvi, wh[64 + lane], hn);
    }
    float r  = 1.0f / (1.0f + expf(-(gr + hr)));
    float z  = 1.0f / (1.0f + expf(-(gz + hz)));
    float nn = tanhf(gn + r * hn);
    float hnew = (1.0f - z) * nn + z * hv;

    if (use_ext) out_ext[warp * D + lane] = hnew;
    else         g_h[warp * D + lane] = hnew;
}

// ===========================================================================
extern "C" void kernel_launch(void* const* d_in, const int* in_sizes, int n_in,
                              void* d_out, int out_size) {
    const float* x     = (const float*)d_in[0];
    const int*   ei    = (const int*)d_in[1];
    const float* ea    = (const float*)d_in[2];
    const float* Wn    = (const float*)d_in[3];
    const float* bn    = (const float*)d_in[4];
    const float* We1   = (const float*)d_in[5];
    const float* be1   = (const float*)d_in[6];
    const float* We2   = (const float*)d_in[7];
    const float* be2   = (const float*)d_in[8];
    const float* Wroot = (const float*)d_in[9];
    const float* bconv = (const float*)d_in[10];
    const float* Wih   = (const float*)d_in[11];
    const float* Whh   = (const float*)d_in[12];
    const float* bih   = (const float*)d_in[13];
    const float* bhh   = (const float*)d_in[14];
    const int* src = ei;
    const int* dst = ei + EE;
    float* out = (float*)d_out;

    cudaFuncSetAttribute(k_wm_mma, cudaFuncAttributeMaxDynamicSharedMemorySize, SM_TOTAL);

    // launch order chosen so k_wm_mma is the 4th launch (ncu capture slot)
    k_node_init<<<(NN * 32 + 255) / 256, 256>>>(x, Wn, bn);
    k_edge_hidden<<<(EE + 1) / 2, 256>>>(ea, We1, be1);
    k_we2t<<<1024, 128>>>(We2);
    int mtiles = (EE + 127) / 128;   // 1172
    k_wm_mma<<<mtiles, 256, SM_TOTAL>>>(be2);

    for (int s = 0; s < STEPS; s++) {
        k_message<<<(EE * 32 + 255) / 256, 256>>>(src, dst);
        int last = (s == STEPS - 1) ? 1 : 0;
        k_gru<<<(NN * 32 + 255) / 256, 256>>>(Wroot, bconv, Wih, Whh, bih, bhh,
                                              out, last);
    }
}